// round 14
// baseline (speedup 1.0000x reference)
#include <cuda_runtime.h>
#include <cstdint>

#define N_NODES 250000
#define N_EDGES 4000000
#define NODE_F  4
#define HID     32
#define NN      50
#define NF      3
#define OUT_C   53
#define TILES   (N_EDGES / 32)
#define NT      4              // tiles per warp

// Scratch (device globals)
__device__ float  g_accC[N_NODES];                 // 1 MB
__device__ __align__(8) float2 g_accMS[N_NODES];   // 2 MB (tail nodes only)
__device__ float g_conc[N_NODES];
__device__ float g_S;
__device__ int   g_ei_is64;
__device__ float g_sc, g_sm, g_ss;                 // b2 . W*[4:36]
__device__ unsigned g_W1t[8 * HID];                // tf32 W1 rows 0..7
__device__ __align__(16) float4 g_epi0[16];        // {uc0, uc1, um0, um1} per col-pair
__device__ __align__(16) float4 g_epi1[16];        // {us0, us1, w8_0, w8_1}
__device__ __align__(8)  float2 g_epi2[16];        // {b0, b1}

__device__ __forceinline__ float softplusf(float x) {
    return fmaxf(x, 0.0f) + log1pf(expf(-fabsf(x)));
}
__device__ __forceinline__ unsigned f2tf32(float f) {
    unsigned u; asm("cvt.rna.tf32.f32 %0, %1;" : "=r"(u) : "f"(f)); return u;
}
__device__ __forceinline__ void mma_tf32(float d[4],
                                         unsigned a0, unsigned a1, unsigned a2, unsigned a3,
                                         unsigned b0, unsigned b1) {
    asm("mma.sync.aligned.m16n8k8.row.col.f32.tf32.tf32.f32 "
        "{%0,%1,%2,%3}, {%4,%5,%6,%7}, {%8,%9}, {%0,%1,%2,%3};"
        : "+f"(d[0]), "+f"(d[1]), "+f"(d[2]), "+f"(d[3])
        : "r"(a0), "r"(a1), "r"(a2), "r"(a3), "r"(b0), "r"(b1));
}

// ---------------------------------------------------------------------------
// Launch 1: prep
// ---------------------------------------------------------------------------
__global__ void prep_kernel(const int* __restrict__ ei32,
                            const float* __restrict__ W1,
                            const float* __restrict__ b1,
                            const float* __restrict__ W2,
                            const float* __restrict__ b2,
                            const float* __restrict__ Wc,
                            const float* __restrict__ Wmu,
                            const float* __restrict__ Wsig)
{
    __shared__ float suc[HID], sum_[HID], sus[HID];
    const int k = threadIdx.x;
    if (k == 0) {
        int z = 0;
        #pragma unroll
        for (int i = 1; i < 64; i += 2) z |= ei32[i];
        g_ei_is64 = (z == 0) ? 1 : 0;
        g_S = 0.0f;
    }
    float uc = 0.f, um = 0.f, us = 0.f;
    #pragma unroll
    for (int m = 0; m < HID; m++) {
        const float w = W2[k * HID + m];
        uc = fmaf(w, Wc[NODE_F + m],   uc);
        um = fmaf(w, Wmu[NODE_F + m],  um);
        us = fmaf(w, Wsig[NODE_F + m], us);
    }
    suc[k] = uc; sum_[k] = um; sus[k] = us;

    #pragma unroll
    for (int d = 0; d < 8; d++) g_W1t[d * HID + k] = f2tf32(W1[d * HID + k]);

    __syncwarp();
    if (k < 16) {
        const int c0 = 2 * k, c1 = 2 * k + 1;
        g_epi0[k] = make_float4(suc[c0], suc[c1], sum_[c0], sum_[c1]);
        g_epi1[k] = make_float4(sus[c0], sus[c1], W1[8 * HID + c0], W1[8 * HID + c1]);
        g_epi2[k] = make_float2(b1[c0], b1[c1]);
    }

    float pc = b2[k] * Wc[NODE_F + k];
    float pm = b2[k] * Wmu[NODE_F + k];
    float ps = b2[k] * Wsig[NODE_F + k];
    #pragma unroll
    for (int off = 16; off > 0; off >>= 1) {
        pc += __shfl_xor_sync(0xffffffffu, pc, off);
        pm += __shfl_xor_sync(0xffffffffu, pm, off);
        ps += __shfl_xor_sync(0xffffffffu, ps, off);
    }
    if (k == 0) { g_sc = pc; g_sm = pm; g_ss = ps; }
}

// ---------------------------------------------------------------------------
// Launch 2 / 3: zero accC, zero accMS (kept separate: edge stays in slot 4)
// ---------------------------------------------------------------------------
__global__ void zeroC_kernel() {
    const int i = blockIdx.x * blockDim.x + threadIdx.x;
    if (i < N_NODES) g_accC[i] = 0.0f;
}
__global__ void zeroMS_kernel() {
    const int i = blockIdx.x * blockDim.x + threadIdx.x;
    if (i < N_NODES && i % NN >= NN - NF) g_accMS[i] = make_float2(0.f, 0.f);
}

// ---------------------------------------------------------------------------
// Launch 4: edge MLP — 4 tiles/warp, register-pipelined direct-fragment
// gathers, predicated alpha/beta path.
// ---------------------------------------------------------------------------
__global__ __launch_bounds__(256) void edge_kernel(
    const float* __restrict__ x,
    const void* __restrict__ ei_raw,
    const float* __restrict__ ea)
{
    __shared__ __align__(16) float4 sE0[16], sE1[16];
    __shared__ __align__(8)  float2 sE2[16];

    const int tid  = threadIdx.x;
    const int warp = tid >> 5;
    const int lane = tid & 31;
    const int grp  = lane >> 2;
    const int tig  = lane & 3;

    if (tid < 16) {
        sE0[tid] = g_epi0[tid];
        sE1[tid] = g_epi1[tid];
        sE2[tid] = g_epi2[tid];
    }
    __syncthreads();

    const int gwarp = blockIdx.x * 8 + warp;
    if (gwarp * NT >= TILES) return;

    const int is64 = g_ei_is64;
    const float sc = g_sc, sm = g_sm, ss = g_ss;
    const unsigned qmask = 0xFu << (grp * 4);

    // B fragments (once per warp)
    unsigned B0[4], B1[4];
    #pragma unroll
    for (int nt = 0; nt < 4; nt++) {
        B0[nt] = g_W1t[tig       * HID + nt * 8 + grp];
        B1[nt] = g_W1t[(tig + 4) * HID + nt * 8 + grp];
    }

    // tile loader: indices -> shuffles -> direct fragment gathers
    auto load_tile = [&](int tt, float& AV, int& RA0, int& RB0, int& RA1, int& RB1,
                         float F[8]) {
        const int e = tt * 32 + lane;
        int rr, cc;
        if (is64) {
            const long long* ei = (const long long*)ei_raw;
            rr = (int)__ldg(ei + e);
            cc = (int)__ldg(ei + N_EDGES + e);
        } else {
            const int* ei = (const int*)ei_raw;
            rr = __ldg(ei + e);
            cc = __ldg(ei + N_EDGES + e);
        }
        AV = __ldg(ea + e);
        RA0 = __shfl_sync(0xffffffffu, rr, grp);
        RB0 = __shfl_sync(0xffffffffu, rr, grp + 8);
        RA1 = __shfl_sync(0xffffffffu, rr, grp + 16);
        RB1 = __shfl_sync(0xffffffffu, rr, grp + 24);
        const int CA0 = __shfl_sync(0xffffffffu, cc, grp);
        const int CB0 = __shfl_sync(0xffffffffu, cc, grp + 8);
        const int CA1 = __shfl_sync(0xffffffffu, cc, grp + 16);
        const int CB1 = __shfl_sync(0xffffffffu, cc, grp + 24);
        F[0] = __ldg(x + (size_t)RA0 * 4 + tig);
        F[1] = __ldg(x + (size_t)RB0 * 4 + tig);
        F[2] = __ldg(x + (size_t)CA0 * 4 + tig);
        F[3] = __ldg(x + (size_t)CB0 * 4 + tig);
        F[4] = __ldg(x + (size_t)RA1 * 4 + tig);
        F[5] = __ldg(x + (size_t)RB1 * 4 + tig);
        F[6] = __ldg(x + (size_t)CA1 * 4 + tig);
        F[7] = __ldg(x + (size_t)CB1 * 4 + tig);
    };

    auto process_tile = [&](float av, int rA0, int rB0, int rA1, int rB1,
                            const float F[8]) {
        #pragma unroll
        for (int h = 0; h < 2; h++) {
            const unsigned a0 = f2tf32(F[h*4+0]), a1 = f2tf32(F[h*4+1]);
            const unsigned a2 = f2tf32(F[h*4+2]), a3 = f2tf32(F[h*4+3]);
            float D[4][4];
            #pragma unroll
            for (int nt = 0; nt < 4; nt++) {
                D[nt][0] = D[nt][1] = D[nt][2] = D[nt][3] = 0.0f;
                mma_tf32(D[nt], a0, a1, a2, a3, B0[nt], B1[nt]);
            }

            const float eaA = __shfl_sync(0xffffffffu, av, h * 16 + grp);
            const float eaB = __shfl_sync(0xffffffffu, av, h * 16 + grp + 8);
            const int rA = h ? rA1 : rA0;
            const int rB = h ? rB1 : rB0;
            const bool needA = (rA % NN >= NN - NF);
            const bool needB = (rB % NN >= NN - NF);
            const bool needMS = needA || needB;        // quad-uniform

            float pcA = 0.f, pcB = 0.f, pmA = 0.f, pmB = 0.f, psA = 0.f, psB = 0.f;
            #pragma unroll
            for (int nt = 0; nt < 4; nt++) {
                const int p = nt * 4 + tig;
                const float4 E1 = sE1[p];   // us0, us1, w8_0, w8_1
                const float2 E2 = sE2[p];   // b0, b1
                const float h0 = fmaxf(fmaf(eaA, E1.z, D[nt][0] + E2.x), 0.f);
                const float h1 = fmaxf(fmaf(eaA, E1.w, D[nt][1] + E2.y), 0.f);
                const float h2 = fmaxf(fmaf(eaB, E1.z, D[nt][2] + E2.x), 0.f);
                const float h3 = fmaxf(fmaf(eaB, E1.w, D[nt][3] + E2.y), 0.f);
                const float4 E0 = sE0[p];   // uc0, uc1, um0, um1
                pcA = fmaf(h0, E0.x, fmaf(h1, E0.y, pcA));
                pcB = fmaf(h2, E0.x, fmaf(h3, E0.y, pcB));
                if (needMS) {
                    pmA = fmaf(h0, E0.z, fmaf(h1, E0.w, pmA));
                    pmB = fmaf(h2, E0.z, fmaf(h3, E0.w, pmB));
                    psA = fmaf(h0, E1.x, fmaf(h1, E1.y, psA));
                    psB = fmaf(h2, E1.x, fmaf(h3, E1.y, psB));
                }
            }

            // quad reduction (lanes of a quad are convergent here)
            pcA += __shfl_xor_sync(qmask, pcA, 1); pcA += __shfl_xor_sync(qmask, pcA, 2);
            pcB += __shfl_xor_sync(qmask, pcB, 1); pcB += __shfl_xor_sync(qmask, pcB, 2);
            if (needMS) {
                pmA += __shfl_xor_sync(qmask, pmA, 1); pmA += __shfl_xor_sync(qmask, pmA, 2);
                pmB += __shfl_xor_sync(qmask, pmB, 1); pmB += __shfl_xor_sync(qmask, pmB, 2);
                psA += __shfl_xor_sync(qmask, psA, 1); psA += __shfl_xor_sync(qmask, psA, 2);
                psB += __shfl_xor_sync(qmask, psB, 1); psB += __shfl_xor_sync(qmask, psB, 2);
            }

            if (tig == 0) {
                asm volatile("red.global.add.f32 [%0], %1;"
                             :: "l"(&g_accC[rA]), "f"(pcA + sc) : "memory");
                asm volatile("red.global.add.f32 [%0], %1;"
                             :: "l"(&g_accC[rB]), "f"(pcB + sc) : "memory");
                if (needA)
                    asm volatile("red.global.add.v2.f32 [%0], {%1, %2};"
                                 :: "l"(&g_accMS[rA]), "f"(pmA + sm), "f"(psA + ss) : "memory");
                if (needB)
                    asm volatile("red.global.add.v2.f32 [%0], {%1, %2};"
                                 :: "l"(&g_accMS[rB]), "f"(pmB + sm), "f"(psB + ss) : "memory");
            }
        }
    };

    // ---- register-pipelined loop over NT contiguous tiles ----
    const int t0 = gwarp * NT;
    float av0; int rA0, rB0, rA1, rB1; float F0[8];
    load_tile(t0, av0, rA0, rB0, rA1, rB1, F0);

    #pragma unroll
    for (int i = 0; i < NT; i++) {
        float av1 = 0.f; int sA0 = 0, sB0 = 0, sA1 = 0, sB1 = 0; float F1[8];
        if (i < NT - 1)
            load_tile(t0 + i + 1, av1, sA0, sB0, sA1, sB1, F1);

        process_tile(av0, rA0, rB0, rA1, rB1, F0);

        av0 = av1; rA0 = sA0; rB0 = sB0; rA1 = sA1; rB1 = sB1;
        #pragma unroll
        for (int q = 0; q < 8; q++) F0[q] = F1[q];
    }
}

// ---------------------------------------------------------------------------
// Launch 5: per-node heads + conc sum
// ---------------------------------------------------------------------------
__global__ __launch_bounds__(256) void node_kernel(
    const float* __restrict__ x,
    const float* __restrict__ Wc,  const float* __restrict__ bc,
    const float* __restrict__ Wmu, const float* __restrict__ bmu,
    const float* __restrict__ Wsig,const float* __restrict__ bsig,
    const float* __restrict__ high,
    float* __restrict__ out)
{
    __shared__ float sWarp[8];
    const int i = blockIdx.x * blockDim.x + threadIdx.x;

    float concv = 0.0f;
    if (i < N_NODES) {
        const float  ac = g_accC[i];
        const float4 xi = __ldg(reinterpret_cast<const float4*>(x) + i);

        const float craw = xi.x * __ldg(Wc+0) + xi.y * __ldg(Wc+1)
                         + xi.z * __ldg(Wc+2) + xi.w * __ldg(Wc+3)
                         + ac + __ldg(bc) + 1e-10f;
        concv = softplusf(craw);
        g_conc[i] = concv;

        const int p = i % NN;
        if (p >= NN - NF) {
            const float2 ms = g_accMS[i];
            const float mraw = xi.x * __ldg(Wmu+0) + xi.y * __ldg(Wmu+1)
                             + xi.z * __ldg(Wmu+2) + xi.w * __ldg(Wmu+3)
                             + ms.x + __ldg(bmu) + 1e-20f;
            const float sraw = xi.x * __ldg(Wsig+0) + xi.y * __ldg(Wsig+1)
                             + xi.z * __ldg(Wsig+2) + xi.w * __ldg(Wsig+3)
                             + ms.y + __ldg(bsig) + 1e-20f;
            const float alpha = softplusf(mraw) + 1e-20f;
            const float beta  = softplusf(sraw) + 1e-20f;
            const int g = i / NN;
            const int j = p - (NN - NF);
            out[g * OUT_C + NN + j] = alpha / (alpha + beta) * __ldg(high + j);
        }
    }

    float s = concv;
    #pragma unroll
    for (int off = 16; off > 0; off >>= 1) s += __shfl_xor_sync(0xffffffffu, s, off);
    if ((threadIdx.x & 31) == 0) sWarp[threadIdx.x >> 5] = s;
    __syncthreads();
    if (threadIdx.x == 0) {
        float tsum = 0.f;
        #pragma unroll
        for (int w = 0; w < 8; w++) tsum += sWarp[w];
        atomicAdd(&g_S, tsum);
    }
}

// ---------------------------------------------------------------------------
// Launch 6: normalize conc
// ---------------------------------------------------------------------------
__global__ void final_kernel(float* __restrict__ out) {
    const int i = blockIdx.x * blockDim.x + threadIdx.x;
    if (i >= N_NODES) return;
    const float invS = 1.0f / (g_S + 1e-20f);
    out[(i / NN) * OUT_C + (i % NN)] = g_conc[i] * invS;
}

// ---------------------------------------------------------------------------
extern "C" void kernel_launch(void* const* d_in, const int* in_sizes, int n_in,
                              void* d_out, int out_size) {
    const float* x    = (const float*)d_in[0];
    const void*  ei   = d_in[1];
    const float* ea   = (const float*)d_in[2];
    const float* high = (const float*)d_in[3];
    const float* W1   = (const float*)d_in[4];
    const float* b1   = (const float*)d_in[5];
    const float* W2   = (const float*)d_in[6];
    const float* b2   = (const float*)d_in[7];
    const float* Wc   = (const float*)d_in[8];
    const float* bc   = (const float*)d_in[9];
    const float* Wmu  = (const float*)d_in[10];
    const float* bmu  = (const float*)d_in[11];
    const float* Wsig = (const float*)d_in[12];
    const float* bsig = (const float*)d_in[13];
    float* out = (float*)d_out;

    const int warps_needed = TILES / NT;                  // 31250
    const int eblocks = (warps_needed + 7) / 8;           // 3907

    prep_kernel  <<<1, 32>>>((const int*)ei, W1, b1, W2, b2, Wc, Wmu, Wsig);
    zeroC_kernel <<<(N_NODES + 255) / 256, 256>>>();
    zeroMS_kernel<<<(N_NODES + 255) / 256, 256>>>();
    edge_kernel  <<<eblocks, 256>>>(x, ei, ea);
    node_kernel  <<<(N_NODES + 255) / 256, 256>>>(x, Wc, bc, Wmu, bmu, Wsig, bsig, high, out);
    final_kernel <<<(N_NODES + 255) / 256, 256>>>(out);
}